// round 1
// baseline (speedup 1.0000x reference)
#include <cuda_runtime.h>
#include <math.h>

// Problem constants
#define BB 4
#define CC 256
#define HH 80
#define WW 80
#define KK9 9
#define NPOS (BB*HH*WW)          // 25600
#define OMCH 32                  // padded 27 -> 32 per-position record

// Scratch (device globals; no allocation allowed)
__device__ __align__(16) float g_xp[BB*HH*WW*CC];   // pooled input, NHWC: [b][h][w][c]
__device__ __align__(16) float g_om[NPOS*OMCH];     // per-pos: [0..17]=offsets, [18..26]=mask
__device__ __align__(16) float g_wre[27*KK9*CC];    // offset/mask weights [oc][kk][c]
__device__ __align__(16) float g_wde[CC*KK9*CC];    // deform weights      [o][kk][c]

// ---------------------------------------------------------------------------
// Kernel 1: 3x3 avg pool (zero pad, /9) NCHW -> NHWC via smem transpose
// grid: b*h*wtile(5)*ctile(16) = 25600 blocks, 256 threads
// ---------------------------------------------------------------------------
__global__ void pool_kernel(const float* __restrict__ x) {
    __shared__ float tile[16][17];
    int id = blockIdx.x;
    int c0 = (id & 15) * 16; id >>= 4;
    int w0 = (id % 5) * 16;  id /= 5;
    int h  = id % HH;
    int b  = id / HH;
    int t  = threadIdx.x;
    int ci = t >> 4, wi = t & 15;
    int c = c0 + ci, wcol = w0 + wi;
    const float* xb = x + ((long)(b*CC + c) * HH) * WW;
    float s = 0.f;
#pragma unroll
    for (int dy = -1; dy <= 1; dy++) {
        int y = h + dy;
        if (y < 0 || y >= HH) continue;
#pragma unroll
        for (int dx = -1; dx <= 1; dx++) {
            int xx = wcol + dx;
            if (xx < 0 || xx >= WW) continue;
            s += xb[y*WW + xx];
        }
    }
    tile[ci][wi] = s * (1.f/9.f);
    __syncthreads();
    int wi2 = t >> 4, ci2 = t & 15;
    g_xp[((b*HH + h)*WW + w0 + wi2)*CC + c0 + ci2] = tile[ci2][wi2];
}

// ---------------------------------------------------------------------------
// Kernel 2: weight re-layout to [oc][kk][c] (c contiguous for float4 loads)
// ---------------------------------------------------------------------------
#define NRE (27*KK9*CC)
#define NDE (CC*KK9*CC)
__global__ void wprep_kernel(const float* __restrict__ off_w,
                             const float* __restrict__ mod_w,
                             const float* __restrict__ w) {
    int i = blockIdx.x * 256 + threadIdx.x;
    if (i < NRE) {
        int c  = i & (CC-1);
        int kk = (i >> 8) % KK9;
        int oc = i / (KK9*CC);
        float v = (oc < 18) ? off_w[(oc*CC + c)*KK9 + kk]
                            : mod_w[((oc-18)*CC + c)*KK9 + kk];
        g_wre[i] = v;
    } else if (i < NRE + NDE) {
        int k  = i - NRE;
        int c  = k & (CC-1);
        int kk = (k >> 8) % KK9;
        int o  = k / (KK9*CC);
        g_wde[k] = w[(o*CC + c)*KK9 + kk];
    }
}

// ---------------------------------------------------------------------------
// Kernel 3: offset+mask 3x3 conv over xp (NHWC).
// warp handles 4 consecutive positions; lane = output channel (0..26).
// grid: 800 blocks x 256 threads (6400 warps x 4 positions = 25600)
// ---------------------------------------------------------------------------
__global__ void __launch_bounds__(256) offmask_kernel(const float* __restrict__ off_b,
                                                      const float* __restrict__ mod_b) {
    int t = threadIdx.x;
    int lane = t & 31;
    int warp = (blockIdx.x << 3) + (t >> 5);
    int p0 = warp * 4;

    int bb[4], hh[4], ww[4];
#pragma unroll
    for (int j = 0; j < 4; j++) {
        int pg = p0 + j;
        bb[j] = pg / (HH*WW);
        int r = pg % (HH*WW);
        hh[j] = r / WW;
        ww[j] = r % WW;
    }

    float acc[4] = {0.f, 0.f, 0.f, 0.f};
    if (lane < 27) {
        const float* wbase = g_wre + lane * KK9 * CC;
        const float4* xp4 = (const float4*)g_xp;
#pragma unroll
        for (int kk = 0; kk < 9; kk++) {
            int ky = kk/3 - 1, kx = kk%3 - 1;
            const float4* wr = (const float4*)(wbase + kk*CC);
            int base[4]; bool val[4];
#pragma unroll
            for (int j = 0; j < 4; j++) {
                int y = hh[j] + ky, xx = ww[j] + kx;
                val[j] = ((unsigned)y < HH) && ((unsigned)xx < WW);
                base[j] = val[j] ? ((bb[j]*HH + y)*WW + xx) * (CC/4) : 0;
            }
            for (int c4 = 0; c4 < CC/4; c4++) {
                float4 wv = wr[c4];
#pragma unroll
                for (int j = 0; j < 4; j++) {
                    if (val[j]) {
                        float4 xv = xp4[base[j] + c4];
                        acc[j] += wv.x*xv.x + wv.y*xv.y + wv.z*xv.z + wv.w*xv.w;
                    }
                }
            }
        }
#pragma unroll
        for (int j = 0; j < 4; j++) {
            float v;
            if (lane < 18) {
                v = acc[j] + off_b[lane];
            } else {
                float a = acc[j] + mod_b[lane - 18];
                v = 2.f / (1.f + expf(-a));
            }
            g_om[(p0 + j)*OMCH + lane] = v;
        }
    }
}

// ---------------------------------------------------------------------------
// Kernel 4: deformable conv. Block = 32 positions x 256 out channels.
// Phase A: precompute 288 (p,k) bilinear corner indices + mask-folded weights.
// Phase B: for 8 chunks of 32 channels: gather s[p][k][c] tile, register GEMM.
// Phase C: smem transpose -> coalesced NCHW store.
// grid: 800 blocks x 256 threads
// ---------------------------------------------------------------------------
#define TILE_P 32
#define NPAIR (TILE_P*KK9)     // 288
#define CCHUNK 32

__global__ void __launch_bounds__(256) deform_kernel(const float* __restrict__ bias,
                                                     float* __restrict__ out) {
    __shared__ float4 sW[NPAIR];
    __shared__ int4   sI[NPAIR];
    __shared__ __align__(16) float sS[NPAIR*CCHUNK];   // 9216 floats = 36 KB
    __shared__ int sOB[TILE_P];

    int t = threadIdx.x;
    int pbase = blockIdx.x * TILE_P;

    // Phase A
    for (int q = t; q < NPAIR; q += 256) {
        int p = q / 9, k = q % 9;
        int pg = pbase + p;
        int b = pg / (HH*WW);
        int r = pg % (HH*WW);
        int h = r / WW, w = r % WW;
        float dy = g_om[pg*OMCH + 2*k];
        float dx = g_om[pg*OMCH + 2*k + 1];
        float m  = g_om[pg*OMCH + 18 + k];
        float py = (float)(h - 1 + k/3) + dy;
        float px = (float)(w - 1 + k%3) + dx;
        float fy = floorf(py), fx = floorf(px);
        int y0 = (int)fy, x0 = (int)fx;
        float wy = py - fy, wx = px - fx;
        int y1 = y0 + 1, x1 = x0 + 1;
        bool vy0 = (unsigned)y0 < HH, vy1 = (unsigned)y1 < HH;
        bool vx0 = (unsigned)x0 < WW, vx1 = (unsigned)x1 < WW;
        float4 wv;
        wv.x = (1.f-wy)*(1.f-wx)*m * (float)(vy0 && vx0);
        wv.y = (1.f-wy)*wx      *m * (float)(vy0 && vx1);
        wv.z = wy*(1.f-wx)      *m * (float)(vy1 && vx0);
        wv.w = wy*wx            *m * (float)(vy1 && vx1);
        int yc0 = min(max(y0, 0), HH-1), yc1 = min(max(y1, 0), HH-1);
        int xc0 = min(max(x0, 0), WW-1), xc1 = min(max(x1, 0), WW-1);
        int rowb = b*HH;
        int4 iv;
        iv.x = ((rowb + yc0)*WW + xc0) * CC;
        iv.y = ((rowb + yc0)*WW + xc1) * CC;
        iv.z = ((rowb + yc1)*WW + xc0) * CC;
        iv.w = ((rowb + yc1)*WW + xc1) * CC;
        sW[q] = wv;
        sI[q] = iv;
    }
    if (t < TILE_P) {
        int pg = pbase + t;
        int b = pg / (HH*WW);
        int r = pg % (HH*WW);
        sOB[t] = b * (CC*HH*WW) + r;   // + o*HH*WW later
    }

    float acc[TILE_P];
#pragma unroll
    for (int p = 0; p < TILE_P; p++) acc[p] = 0.f;

    const int o = t;
    const float* wp = g_wde + o * KK9 * CC;

    for (int cb = 0; cb < CC/CCHUNK; cb++) {
        int c0 = cb * CCHUNK;
        __syncthreads();
        // gather tile: s[q][c], q = p*9+k
        for (int e = t; e < NPAIR*CCHUNK; e += 256) {
            int q = e >> 5;
            int c = (e & 31) + c0;
            float4 wv = sW[q];
            int4 iv = sI[q];
            sS[e] = wv.x * g_xp[iv.x + c] + wv.y * g_xp[iv.y + c]
                  + wv.z * g_xp[iv.z + c] + wv.w * g_xp[iv.w + c];
        }
        __syncthreads();
        // GEMM: acc[p] += sum_{kk,c} s[p][kk][c] * w[o][kk][c]
        for (int kk = 0; kk < 9; kk++) {
            const float4* w4 = (const float4*)(wp + kk*CC + c0);
            const float4* s4 = (const float4*)sS;
            for (int c4 = 0; c4 < CCHUNK/4; c4++) {
                float4 wv = w4[c4];
#pragma unroll
                for (int p = 0; p < TILE_P; p++) {
                    float4 sv = s4[(p*9 + kk)*(CCHUNK/4) + c4];
                    acc[p] += wv.x*sv.x + wv.y*sv.y + wv.z*sv.z + wv.w*sv.w;
                }
            }
        }
    }

    // Phase C: transpose through smem, coalesced store (NCHW)
    __syncthreads();
    float bo = bias[o];
#pragma unroll
    for (int p = 0; p < TILE_P; p++) {
        sS[p*257 + o] = acc[p] + bo;     // 32*257 = 8224 <= 9216
    }
    __syncthreads();
#pragma unroll
    for (int i = 0; i < 32; i++) {
        int oo = (i << 3) + (t >> 5);    // warp-uniform channel
        int p  = t & 31;                  // lane = position -> consecutive w
        out[sOB[p] + oo*(HH*WW)] = sS[p*257 + oo];
    }
}

// ---------------------------------------------------------------------------
extern "C" void kernel_launch(void* const* d_in, const int* in_sizes, int n_in,
                              void* d_out, int out_size) {
    const float* x     = (const float*)d_in[0];
    const float* off_w = (const float*)d_in[1];
    const float* off_b = (const float*)d_in[2];
    const float* mod_w = (const float*)d_in[3];
    const float* mod_b = (const float*)d_in[4];
    const float* w     = (const float*)d_in[5];
    const float* b     = (const float*)d_in[6];
    float* out = (float*)d_out;

    pool_kernel<<<BB*HH*5*16, 256>>>(x);
    wprep_kernel<<<(NRE + NDE + 255)/256, 256>>>(off_w, mod_w, w);
    offmask_kernel<<<NPOS/32, 256>>>(off_b, mod_b);
    deform_kernel<<<NPOS/TILE_P, 256>>>(b, out);
}

// round 2
// speedup vs baseline: 1.4089x; 1.4089x over previous
#include <cuda_runtime.h>
#include <math.h>

// Problem constants
#define BB 4
#define CC 256
#define HH 80
#define WW 80
#define KK9 9
#define HW (HH*WW)
#define NPOS (BB*HW)             // 25600

// Scratch (device globals; no allocation allowed)
__device__ __align__(16) float g_xp[NPOS*CC];         // pooled input NHWC
__device__ __align__(16) float g_om[NPOS*32];         // per-pos offsets(18)+mask(9)
__device__ __align__(16) float g_wre2[KK9*64*32*4];   // offmask W: [kk][c4][oc(32)][4]
__device__ __align__(16) float g_wde[CC*KK9*CC];      // deform W: [o][kk][c]

union F4 { float4 f; unsigned long long u[2]; };

__device__ __forceinline__ unsigned long long ff2(unsigned long long a,
                                                  unsigned long long b,
                                                  unsigned long long c) {
    unsigned long long d;
    asm("fma.rn.f32x2 %0, %1, %2, %3;" : "=l"(d) : "l"(a), "l"(b), "l"(c));
    return d;
}

// ---------------------------------------------------------------------------
// Kernel 1: 3x3 avg pool (zero pad, /9) NCHW -> NHWC via smem transpose
// ---------------------------------------------------------------------------
__global__ void pool_kernel(const float* __restrict__ x) {
    __shared__ float tile[16][17];
    int id = blockIdx.x;
    int c0 = (id & 15) * 16; id >>= 4;
    int w0 = (id % 5) * 16;  id /= 5;
    int h  = id % HH;
    int b  = id / HH;
    int t  = threadIdx.x;
    int ci = t >> 4, wi = t & 15;
    int c = c0 + ci, wcol = w0 + wi;
    const float* xb = x + ((long)(b*CC + c) * HH) * WW;
    float s = 0.f;
#pragma unroll
    for (int dy = -1; dy <= 1; dy++) {
        int y = h + dy;
        if (y < 0 || y >= HH) continue;
#pragma unroll
        for (int dx = -1; dx <= 1; dx++) {
            int xx = wcol + dx;
            if (xx < 0 || xx >= WW) continue;
            s += xb[y*WW + xx];
        }
    }
    tile[ci][wi] = s * (1.f/9.f);
    __syncthreads();
    int wi2 = t >> 4, ci2 = t & 15;
    g_xp[((b*HH + h)*WW + w0 + wi2)*CC + c0 + ci2] = tile[ci2][wi2];
}

// ---------------------------------------------------------------------------
// Kernel 2: weight re-layouts
//   g_wre2: [kk][c4(64)][oc(32 padded)][4]  (coalesced over oc for offmask)
//   g_wde:  [o][kk][c]                      (float4 over c for deform)
// ---------------------------------------------------------------------------
#define NRE2 (KK9*64*32*4)       // 73728
#define NDE  (CC*KK9*CC)         // 589824
__global__ void wprep_kernel(const float* __restrict__ off_w,
                             const float* __restrict__ mod_w,
                             const float* __restrict__ w) {
    int i = blockIdx.x * 256 + threadIdx.x;
    if (i < NRE2) {
        int r  = i & 3;
        int oc = (i >> 2) & 31;
        int c4 = (i >> 7) & 63;
        int kk = i >> 13;
        int c  = c4*4 + r;
        float v = 0.f;
        if (oc < 18)      v = off_w[(oc*CC + c)*KK9 + kk];
        else if (oc < 27) v = mod_w[((oc-18)*CC + c)*KK9 + kk];
        g_wre2[i] = v;
    } else if (i < NRE2 + NDE) {
        int k  = i - NRE2;
        int c  = k & (CC-1);
        int kk = (k >> 8) % KK9;
        int o  = k / (KK9*CC);
        g_wde[k] = w[(o*CC + c)*KK9 + kk];
    }
}

// ---------------------------------------------------------------------------
// Kernel 3: offset+mask conv. Block = 32 positions x 32(27) out channels.
// im2col chunk tile in smem, f32x2 GEMM. thread: o = t&31, pg = t>>5 (4 p each)
// ---------------------------------------------------------------------------
#define OM_P 32
#define CSTR 20                   // padded s-row stride (floats)

__global__ void __launch_bounds__(256) offmask_kernel(const float* __restrict__ off_b,
                                                      const float* __restrict__ mod_b) {
    __shared__ float sX[OM_P*KK9*CSTR];    // 5760 floats
    __shared__ int sBase[OM_P*KK9];

    int t = threadIdx.x;
    int pbase = blockIdx.x * OM_P;
    int o  = t & 31;
    int pg = t >> 5;

    for (int q = t; q < OM_P*KK9; q += 256) {
        int p = q / 9, k = q % 9;
        int pgl = pbase + p;
        int b = pgl / HW;
        int r = pgl % HW;
        int h = r / WW, w_ = r % WW;
        int y = h - 1 + k/3, x = w_ - 1 + k%3;
        sBase[q] = (((unsigned)y < HH) && ((unsigned)x < WW))
                   ? ((b*HH + y)*WW + x)*CC : -1;
    }

    unsigned long long acc[4] = {0ull, 0ull, 0ull, 0ull};

    for (int cb = 0; cb < 16; cb++) {
        int c0 = cb * 16;
        __syncthreads();
        for (int e = t; e < OM_P*KK9*16; e += 256) {
            int q = e >> 4, c = e & 15;
            int bi = sBase[q];
            sX[q*CSTR + c] = (bi >= 0) ? g_xp[bi + c0 + c] : 0.f;
        }
        __syncthreads();
#pragma unroll
        for (int kk = 0; kk < 9; kk++) {
#pragma unroll
            for (int c4 = 0; c4 < 4; c4++) {
                F4 wv;
                wv.f = *(const float4*)&g_wre2[((kk*64 + cb*4 + c4)*32 + o)*4];
#pragma unroll
                for (int j = 0; j < 4; j++) {
                    int p = pg + 8*j;
                    F4 sv;
                    sv.f = *(const float4*)&sX[(p*9 + kk)*CSTR + c4*4];
                    acc[j] = ff2(sv.u[0], wv.u[0], acc[j]);
                    acc[j] = ff2(sv.u[1], wv.u[1], acc[j]);
                }
            }
        }
    }

    if (o < 27) {
#pragma unroll
        for (int j = 0; j < 4; j++) {
            float2 f = *(float2*)&acc[j];
            float r = f.x + f.y;
            float v;
            if (o < 18) v = r + off_b[o];
            else { float a = r + mod_b[o-18]; v = 2.f/(1.f + expf(-a)); }
            g_om[(pbase + pg + 8*j)*32 + o] = v;
        }
    }
}

// ---------------------------------------------------------------------------
// Kernel 4: deformable conv. Block = 32 positions x 256 out channels.
// thread: pg = t&7 (4 p, stride 8), og = t>>3 (8 o). f32x2 GEMM, 4p x 8o tile.
// ---------------------------------------------------------------------------
#define DF_P 32
#define NPAIR (DF_P*KK9)          // 288

__global__ void __launch_bounds__(256) deform_kernel(const float* __restrict__ bias,
                                                     float* __restrict__ out) {
    __shared__ float4 sW[NPAIR];
    __shared__ int4   sI[NPAIR];
    __shared__ __align__(16) float sS[NPAIR*CSTR];   // 5760 floats
    __shared__ int sOB[DF_P];

    int t = threadIdx.x;
    int pbase = blockIdx.x * DF_P;

    // Phase A: bilinear corner indices + mask-folded weights
    for (int q = t; q < NPAIR; q += 256) {
        int p = q / 9, k = q % 9;
        int pgl = pbase + p;
        int b = pgl / HW;
        int r = pgl % HW;
        int h = r / WW, w = r % WW;
        float dy = g_om[pgl*32 + 2*k];
        float dx = g_om[pgl*32 + 2*k + 1];
        float m  = g_om[pgl*32 + 18 + k];
        float py = (float)(h - 1 + k/3) + dy;
        float px = (float)(w - 1 + k%3) + dx;
        float fy = floorf(py), fx = floorf(px);
        int y0 = (int)fy, x0 = (int)fx;
        float wy = py - fy, wx = px - fx;
        int y1 = y0 + 1, x1 = x0 + 1;
        bool vy0 = (unsigned)y0 < HH, vy1 = (unsigned)y1 < HH;
        bool vx0 = (unsigned)x0 < WW, vx1 = (unsigned)x1 < WW;
        float4 wv;
        wv.x = (1.f-wy)*(1.f-wx)*m * (float)(vy0 && vx0);
        wv.y = (1.f-wy)*wx      *m * (float)(vy0 && vx1);
        wv.z = wy*(1.f-wx)      *m * (float)(vy1 && vx0);
        wv.w = wy*wx            *m * (float)(vy1 && vx1);
        int yc0 = min(max(y0, 0), HH-1), yc1 = min(max(y1, 0), HH-1);
        int xc0 = min(max(x0, 0), WW-1), xc1 = min(max(x1, 0), WW-1);
        int rowb = b*HH;
        int4 iv;
        iv.x = ((rowb + yc0)*WW + xc0) * CC;
        iv.y = ((rowb + yc0)*WW + xc1) * CC;
        iv.z = ((rowb + yc1)*WW + xc0) * CC;
        iv.w = ((rowb + yc1)*WW + xc1) * CC;
        sW[q] = wv;
        sI[q] = iv;
    }
    if (t < DF_P) {
        int pgl = pbase + t;
        sOB[t] = (pgl / HW) * (CC*HW) + (pgl % HW);
    }

    int pg = t & 7;
    int og = t >> 3;
    unsigned long long acc[4][8];
#pragma unroll
    for (int j = 0; j < 4; j++)
#pragma unroll
        for (int i = 0; i < 8; i++) acc[j][i] = 0ull;

    for (int cb = 0; cb < 16; cb++) {
        int c0 = cb * 16;
        __syncthreads();
        // gather chunk: s[q][c] = bilinear sample, mask folded in
        for (int e = t; e < NPAIR*16; e += 256) {
            int q = e >> 4;
            int c = (e & 15) + c0;
            float4 wv = sW[q];
            int4 iv = sI[q];
            sS[q*CSTR + (e & 15)] =
                  wv.x * g_xp[iv.x + c] + wv.y * g_xp[iv.y + c]
                + wv.z * g_xp[iv.z + c] + wv.w * g_xp[iv.w + c];
        }
        __syncthreads();
#pragma unroll 1
        for (int kk = 0; kk < 9; kk++) {
#pragma unroll
            for (int c4 = 0; c4 < 4; c4++) {
                F4 sv[4];
#pragma unroll
                for (int j = 0; j < 4; j++)
                    sv[j].f = *(const float4*)&sS[((pg + 8*j)*9 + kk)*CSTR + c4*4];
#pragma unroll
                for (int i = 0; i < 8; i++) {
                    int o = og*8 + i;
                    F4 wv;
                    wv.f = *(const float4*)&g_wde[(o*9 + kk)*CC + c0 + c4*4];
#pragma unroll
                    for (int j = 0; j < 4; j++) {
                        acc[j][i] = ff2(sv[j].u[0], wv.u[0], acc[j][i]);
                        acc[j][i] = ff2(sv[j].u[1], wv.u[1], acc[j][i]);
                    }
                }
            }
        }
    }

    // store (4 consecutive-p lanes per 8-lane group -> 32B segments)
#pragma unroll
    for (int i = 0; i < 8; i++) {
        int o = og*8 + i;
        float bo = bias[o];
#pragma unroll
        for (int j = 0; j < 4; j++) {
            float2 f = *(float2*)&acc[j][i];
            out[sOB[pg + 8*j] + o*HW] = f.x + f.y + bo;
        }
    }
}

// ---------------------------------------------------------------------------
extern "C" void kernel_launch(void* const* d_in, const int* in_sizes, int n_in,
                              void* d_out, int out_size) {
    const float* x     = (const float*)d_in[0];
    const float* off_w = (const float*)d_in[1];
    const float* off_b = (const float*)d_in[2];
    const float* mod_w = (const float*)d_in[3];
    const float* mod_b = (const float*)d_in[4];
    const float* w     = (const float*)d_in[5];
    const float* b     = (const float*)d_in[6];
    float* out = (float*)d_out;

    pool_kernel<<<BB*HH*5*16, 256>>>(x);
    wprep_kernel<<<(NRE2 + NDE + 255)/256, 256>>>(off_w, mod_w, w);
    offmask_kernel<<<NPOS/OM_P, 256>>>(off_b, mod_b);
    deform_kernel<<<NPOS/DF_P, 256>>>(b, out);
}

// round 3
// speedup vs baseline: 1.4320x; 1.0165x over previous
#include <cuda_runtime.h>
#include <math.h>

// Problem constants
#define BB 4
#define CC 256
#define HH 80
#define WW 80
#define KK9 9
#define HW (HH*WW)
#define NPOS (BB*HW)             // 25600

// Scratch (device globals; no allocation allowed)
__device__ __align__(16) float g_xp[NPOS*CC];         // pooled input NHWC
__device__ __align__(16) float g_om[NPOS*32];         // per-pos offsets(18)+mask(9)
__device__ __align__(16) float g_wre2[KK9*64*32*4];   // offmask W: [kk][c4][oc(32)][4]
__device__ __align__(16) float g_wde2[KK9*64*256*4];  // deform W: [kk][c4][o][4]

union F4 { float4 f; unsigned long long u[2]; };

__device__ __forceinline__ unsigned long long ff2(unsigned long long a,
                                                  unsigned long long b,
                                                  unsigned long long c) {
    unsigned long long d;
    asm("fma.rn.f32x2 %0, %1, %2, %3;" : "=l"(d) : "l"(a), "l"(b), "l"(c));
    return d;
}

// ---------------------------------------------------------------------------
// Kernel 1: 3x3 avg pool (zero pad, /9) NCHW -> NHWC via smem transpose
// ---------------------------------------------------------------------------
__global__ void pool_kernel(const float* __restrict__ x) {
    __shared__ float tile[16][17];
    int id = blockIdx.x;
    int c0 = (id & 15) * 16; id >>= 4;
    int w0 = (id % 5) * 16;  id /= 5;
    int h  = id % HH;
    int b  = id / HH;
    int t  = threadIdx.x;
    int ci = t >> 4, wi = t & 15;
    int c = c0 + ci, wcol = w0 + wi;
    const float* xb = x + ((long)(b*CC + c) * HH) * WW;
    float s = 0.f;
#pragma unroll
    for (int dy = -1; dy <= 1; dy++) {
        int y = h + dy;
        if (y < 0 || y >= HH) continue;
#pragma unroll
        for (int dx = -1; dx <= 1; dx++) {
            int xx = wcol + dx;
            if (xx < 0 || xx >= WW) continue;
            s += xb[y*WW + xx];
        }
    }
    tile[ci][wi] = s * (1.f/9.f);
    __syncthreads();
    int wi2 = t >> 4, ci2 = t & 15;
    g_xp[((b*HH + h)*WW + w0 + wi2)*CC + c0 + ci2] = tile[ci2][wi2];
}

// ---------------------------------------------------------------------------
// Kernel 2: weight re-layouts: [kk][c4][oc][4] for both convs
// ---------------------------------------------------------------------------
#define NRE2 (KK9*64*32*4)       // 73728
#define NDE2 (KK9*64*256*4)      // 589824
__global__ void wprep_kernel(const float* __restrict__ off_w,
                             const float* __restrict__ mod_w,
                             const float* __restrict__ w) {
    int i = blockIdx.x * 256 + threadIdx.x;
    if (i < NRE2) {
        int r  = i & 3;
        int oc = (i >> 2) & 31;
        int c4 = (i >> 7) & 63;
        int kk = i >> 13;
        int c  = c4*4 + r;
        float v = 0.f;
        if (oc < 18)      v = off_w[(oc*CC + c)*KK9 + kk];
        else if (oc < 27) v = mod_w[((oc-18)*CC + c)*KK9 + kk];
        g_wre2[i] = v;
    } else if (i < NRE2 + NDE2) {
        int k  = i - NRE2;
        int r  = k & 3;
        int o  = (k >> 2) & 255;
        int c4 = (k >> 10) & 63;
        int kk = k >> 16;
        int c  = c4*4 + r;
        g_wde2[k] = w[(o*CC + c)*KK9 + kk];
    }
}

// ---------------------------------------------------------------------------
// Kernel 3: offset+mask conv. Block = 64 threads = 2 warps, each warp 32 pos.
// lane = position, o-loop over 27, weights staged in smem (broadcast reads).
// ---------------------------------------------------------------------------
#define OM_CSTR 12

__global__ void __launch_bounds__(64) offmask_kernel(const float* __restrict__ off_b,
                                                     const float* __restrict__ mod_b) {
    __shared__ __align__(16) float sX[2*32*KK9*OM_CSTR];  // 2 warps x 3456
    __shared__ __align__(16) float4 sWr[KK9*2*32];        // [kk*2+j][oc]
    __shared__ int sBase[2*32*KK9];                       // f4 index or -1

    int t = threadIdx.x;
    int lane = t & 31, wi = t >> 5;
    int pbase = blockIdx.x * 64;
    const float4* xp4 = (const float4*)g_xp;
    const float4* wre4 = (const float4*)g_wre2;

    for (int q = t; q < 576; q += 64) {
        int w2 = q / 288, qq = q % 288;
        int p = qq / 9, k = qq % 9;
        int pgl = pbase + w2*32 + p;
        int b = pgl / HW;
        int r = pgl % HW;
        int h = r / WW, w_ = r % WW;
        int y = h - 1 + k/3, x = w_ - 1 + k%3;
        sBase[q] = (((unsigned)y < HH) && ((unsigned)x < WW))
                   ? ((b*HH + y)*WW + x)*(CC/4) : -1;
    }
    __syncthreads();

    float* sXw = sX + wi*3456;
    const int* sBw = sBase + wi*288;
    unsigned long long acc[27];
#pragma unroll
    for (int o = 0; o < 27; o++) acc[o] = 0ull;

    for (int cb = 0; cb < 32; cb++) {
        __syncthreads();
        // stage weights for this 8-channel chunk: 576 float4
        for (int i = t; i < 576; i += 64) {
            int oc = i & 31, kkj = i >> 5;
            sWr[kkj*32 + oc] = wre4[((kkj>>1)*64 + cb*2 + (kkj&1))*32 + oc];
        }
        // gather im2col chunk (per warp): 576 float4
        for (int e = lane; e < 576; e += 32) {
            int q = e >> 1, j = e & 1;
            int bi = sBw[q];
            float4 v = make_float4(0.f, 0.f, 0.f, 0.f);
            if (bi >= 0) v = xp4[bi + cb*2 + j];
            *(float4*)&sXw[q*OM_CSTR + j*4] = v;
        }
        __syncthreads();
#pragma unroll 1
        for (int kk = 0; kk < 9; kk++) {
#pragma unroll
            for (int j = 0; j < 2; j++) {
                F4 sv;
                sv.f = *(const float4*)&sXw[(lane*9 + kk)*OM_CSTR + j*4];
                const float4* wrow = &sWr[(kk*2 + j)*32];
#pragma unroll
                for (int o = 0; o < 27; o++) {
                    F4 wv; wv.f = wrow[o];
                    acc[o] = ff2(sv.u[0], wv.u[0], acc[o]);
                    acc[o] = ff2(sv.u[1], wv.u[1], acc[o]);
                }
            }
        }
    }

    int pgl = pbase + wi*32 + lane;
#pragma unroll
    for (int o = 0; o < 27; o++) {
        float2 f = *(float2*)&acc[o];
        float r = f.x + f.y;
        float v;
        if (o < 18) v = r + off_b[o];
        else { float a = r + mod_b[o-18]; v = 2.f/(1.f + expf(-a)); }
        g_om[pgl*32 + o] = v;
    }
}

// ---------------------------------------------------------------------------
// Kernel 4: deformable conv. Block = 32 positions x 256 out channels.
// warp w: lane = position, o in [32w, 32w+32). Weights staged per 8-c chunk,
// read as warp-uniform broadcasts. f32x2 accumulate.
// ---------------------------------------------------------------------------
#define DF_P 32
#define NPAIR (DF_P*KK9)          // 288
#define DF_CSTR 12
// dynamic smem layout (floats):
//   sS   [288*12]          13824 B
//   sWt4 [9*2*256] float4  73728 B
//   sW4  [288]    float4    4608 B
//   sI4  [288]    int4      4608 B
//   sOB  [32]     int        128 B
#define SMEM_DEFORM (288*12*4 + 9*2*256*16 + 288*16 + 288*16 + 128)

__global__ void __launch_bounds__(256, 2) deform_kernel(const float* __restrict__ bias,
                                                        float* __restrict__ out) {
    extern __shared__ __align__(16) float dsm[];
    float*  sS   = dsm;
    float4* sWt4 = (float4*)(dsm + 288*DF_CSTR);
    float4* sW4  = sWt4 + 9*2*256;
    int4*   sI4  = (int4*)(sW4 + NPAIR);
    int*    sOB  = (int*)(sI4 + NPAIR);

    int t = threadIdx.x;
    int pbase = blockIdx.x * DF_P;
    const float4* xp4 = (const float4*)g_xp;
    const float4* wde4 = (const float4*)g_wde2;

    // Phase A: bilinear corner f4-indices + mask-folded weights
    for (int q = t; q < NPAIR; q += 256) {
        int p = q / 9, k = q % 9;
        int pgl = pbase + p;
        int b = pgl / HW;
        int r = pgl % HW;
        int h = r / WW, w = r % WW;
        float dy = g_om[pgl*32 + 2*k];
        float dx = g_om[pgl*32 + 2*k + 1];
        float m  = g_om[pgl*32 + 18 + k];
        float py = (float)(h - 1 + k/3) + dy;
        float px = (float)(w - 1 + k%3) + dx;
        float fy = floorf(py), fx = floorf(px);
        int y0 = (int)fy, x0 = (int)fx;
        float wy = py - fy, wx = px - fx;
        int y1 = y0 + 1, x1 = x0 + 1;
        bool vy0 = (unsigned)y0 < HH, vy1 = (unsigned)y1 < HH;
        bool vx0 = (unsigned)x0 < WW, vx1 = (unsigned)x1 < WW;
        float4 wv;
        wv.x = (1.f-wy)*(1.f-wx)*m * (float)(vy0 && vx0);
        wv.y = (1.f-wy)*wx      *m * (float)(vy0 && vx1);
        wv.z = wy*(1.f-wx)      *m * (float)(vy1 && vx0);
        wv.w = wy*wx            *m * (float)(vy1 && vx1);
        int yc0 = min(max(y0, 0), HH-1), yc1 = min(max(y1, 0), HH-1);
        int xc0 = min(max(x0, 0), WW-1), xc1 = min(max(x1, 0), WW-1);
        int rowb = b*HH;
        int4 iv;
        iv.x = ((rowb + yc0)*WW + xc0) * (CC/4);
        iv.y = ((rowb + yc0)*WW + xc1) * (CC/4);
        iv.z = ((rowb + yc1)*WW + xc0) * (CC/4);
        iv.w = ((rowb + yc1)*WW + xc1) * (CC/4);
        sW4[q] = wv;
        sI4[q] = iv;
    }
    if (t < DF_P) {
        int pgl = pbase + t;
        sOB[t] = (pgl / HW) * (CC*HW) + (pgl % HW);
    }

    int lane = t & 31;
    int w = t >> 5;
    int p9 = lane * 9;
    unsigned long long acc[32];
#pragma unroll
    for (int i = 0; i < 32; i++) acc[i] = 0ull;

    for (int cb = 0; cb < 32; cb++) {
        __syncthreads();
        // stage weight chunk: [kk*2+j][o] float4, 4608 f4, coalesced over o
        for (int i = t; i < 4608; i += 256) {
            int o = i & 255, kkj = i >> 8;
            sWt4[kkj*256 + o] = wde4[((kkj>>1)*64 + cb*2 + (kkj&1))*256 + o];
        }
        // gather bilinear chunk: 576 f4
        for (int e = t; e < 576; e += 256) {
            int q = e >> 1, j = e & 1;
            float4 bw = sW4[q];
            int4 iv = sI4[q];
            int co = cb*2 + j;
            float4 a = xp4[iv.x + co];
            float4 b2 = xp4[iv.y + co];
            float4 c2 = xp4[iv.z + co];
            float4 d2 = xp4[iv.w + co];
            float4 r;
            r.x = bw.x*a.x + bw.y*b2.x + bw.z*c2.x + bw.w*d2.x;
            r.y = bw.x*a.y + bw.y*b2.y + bw.z*c2.y + bw.w*d2.y;
            r.z = bw.x*a.z + bw.y*b2.z + bw.z*c2.z + bw.w*d2.z;
            r.w = bw.x*a.w + bw.y*b2.w + bw.z*c2.w + bw.w*d2.w;
            *(float4*)&sS[q*DF_CSTR + j*4] = r;
        }
        __syncthreads();
#pragma unroll 1
        for (int kk = 0; kk < 9; kk++) {
#pragma unroll
            for (int j = 0; j < 2; j++) {
                F4 sv;
                sv.f = *(const float4*)&sS[(p9 + kk)*DF_CSTR + j*4];
                const float4* wrow = &sWt4[(kk*2 + j)*256 + w*32];
#pragma unroll
                for (int i = 0; i < 32; i++) {
                    F4 wv; wv.f = wrow[i];
                    acc[i] = ff2(sv.u[0], wv.u[0], acc[i]);
                    acc[i] = ff2(sv.u[1], wv.u[1], acc[i]);
                }
            }
        }
    }

    int ob = sOB[lane];
#pragma unroll
    for (int i = 0; i < 32; i++) {
        int o = w*32 + i;
        float2 f = *(float2*)&acc[i];
        out[ob + o*HW] = f.x + f.y + bias[o];
    }
}

// ---------------------------------------------------------------------------
extern "C" void kernel_launch(void* const* d_in, const int* in_sizes, int n_in,
                              void* d_out, int out_size) {
    const float* x     = (const float*)d_in[0];
    const float* off_w = (const float*)d_in[1];
    const float* off_b = (const float*)d_in[2];
    const float* mod_w = (const float*)d_in[3];
    const float* mod_b = (const float*)d_in[4];
    const float* w     = (const float*)d_in[5];
    const float* b     = (const float*)d_in[6];
    float* out = (float*)d_out;

    cudaFuncSetAttribute(deform_kernel,
                         cudaFuncAttributeMaxDynamicSharedMemorySize, SMEM_DEFORM);

    pool_kernel<<<BB*HH*5*16, 256>>>(x);
    wprep_kernel<<<(NRE2 + NDE2 + 255)/256, 256>>>(off_w, mod_w, w);
    offmask_kernel<<<NPOS/64, 64>>>(off_b, mod_b);
    deform_kernel<<<NPOS/DF_P, 256, SMEM_DEFORM>>>(b, out);
}

// round 5
// speedup vs baseline: 3.3518x; 2.3406x over previous
#include <cuda_runtime.h>
#include <cuda_bf16.h>
#include <stdint.h>
#include <math.h>

// Problem constants
#define BB 4
#define CC 256
#define HH 80
#define WW 80
#define KK9 9
#define HW (HH*WW)
#define NPOS (BB*HW)             // 25600
#define NKB 36                   // K chunks: 9 taps x 4 chunks of 64 channels

// Scratch (device globals; no allocation allowed)
__device__ __align__(16) float g_xp[NPOS*CC];         // pooled input NHWC
__device__ __align__(16) float g_tmp[NPOS*CC];        // horizontal pool sums (NCHW)
__device__ __align__(16) float g_om[NPOS*32];         // per-pos offsets(18)+mask(9)
__device__ __align__(16) float g_wre2[KK9*64*32*4];   // offmask W: [kk][c4][oc(32)][4]
__device__ __align__(16) uint2 g_wf[NKB*8*32*32];     // deform W in B-fragment order
                                                       // [kb][bsel(4 khalf x hi/lo)][ntile][lane]

// ============================ helpers ============================
__device__ __forceinline__ uint32_t smem_u32(const void* p) {
    uint32_t a;
    asm("{ .reg .u64 t; cvta.to.shared.u64 t, %1; cvt.u32.u64 %0, t; }" : "=r"(a) : "l"(p));
    return a;
}

__device__ __forceinline__ void ldsm4(uint32_t& a0, uint32_t& a1, uint32_t& a2,
                                      uint32_t& a3, uint32_t addr) {
    asm volatile("ldmatrix.sync.aligned.m8n8.x4.shared.b16 {%0,%1,%2,%3}, [%4];"
        : "=r"(a0), "=r"(a1), "=r"(a2), "=r"(a3) : "r"(addr));
}

__device__ __forceinline__ void mma16816(float* d, uint32_t a0, uint32_t a1,
                                         uint32_t a2, uint32_t a3,
                                         uint32_t b0, uint32_t b1) {
    asm volatile("mma.sync.aligned.m16n8k16.row.col.f32.bf16.bf16.f32 "
        "{%0,%1,%2,%3}, {%4,%5,%6,%7}, {%8,%9}, {%0,%1,%2,%3};"
        : "+f"(d[0]), "+f"(d[1]), "+f"(d[2]), "+f"(d[3])
        : "r"(a0), "r"(a1), "r"(a2), "r"(a3), "r"(b0), "r"(b1));
}

union F4 { float4 f; unsigned long long u[2]; };
__device__ __forceinline__ unsigned long long ff2(unsigned long long a,
                                                  unsigned long long b,
                                                  unsigned long long c) {
    unsigned long long d;
    asm("fma.rn.f32x2 %0, %1, %2, %3;" : "=l"(d) : "l"(a), "l"(b), "l"(c));
    return d;
}

__device__ __forceinline__ uint32_t pack_bf16(float lo_k, float hi_k) {
    __nv_bfloat16 a = __float2bfloat16_rn(lo_k);
    __nv_bfloat16 b = __float2bfloat16_rn(hi_k);
    return ((uint32_t)__bfloat16_as_ushort(b) << 16) | __bfloat16_as_ushort(a);
}

// ---------------------------------------------------------------------------
// Kernel 1a: horizontal 3-sum (NCHW -> g_tmp NCHW)
// ---------------------------------------------------------------------------
__global__ void pool_h(const float* __restrict__ x) {
    int i = blockIdx.x * 256 + threadIdx.x;
    int w = i % WW;
    float s = x[i];
    if (w > 0)      s += x[i-1];
    if (w < WW-1)   s += x[i+1];
    g_tmp[i] = s;
}

// ---------------------------------------------------------------------------
// Kernel 1b: vertical 3-sum + /9 + transpose to NHWC (g_tmp -> g_xp)
// ---------------------------------------------------------------------------
__global__ void pool_v() {
    __shared__ float tile[16][17];
    int id = blockIdx.x;
    int c0 = (id & 15) * 16; id >>= 4;
    int w0 = (id % 5) * 16;  id /= 5;
    int h  = id % HH;
    int b  = id / HH;
    int t  = threadIdx.x;
    int ci = t >> 4, wi = t & 15;
    int c = c0 + ci, wcol = w0 + wi;
    const float* xb = g_tmp + (b*CC + c) * HW;
    float s = 0.f;
#pragma unroll
    for (int dy = -1; dy <= 1; dy++) {
        int y = h + dy;
        if (y < 0 || y >= HH) continue;
        s += xb[y*WW + wcol];
    }
    tile[ci][wi] = s * (1.f/9.f);
    __syncthreads();
    int wi2 = t >> 4, ci2 = t & 15;
    g_xp[((b*HH + h)*WW + w0 + wi2)*CC + c0 + ci2] = tile[ci2][wi2];
}

// ---------------------------------------------------------------------------
// Kernel 2: weight prep
//  - g_wre2 (offmask): [kk][c4][oc(32)][4] fp32
//  - g_wf   (deform):  B fragments for mma.m16n8k16.row.col:
//      record (kb, bsel, ntile): lane l holds uint2
//        .x = bf16pair( w[o][c0], w[o][c0+1] ), .y = pair( w[o][c0+8], w[o][c0+9] )
//      o = ntile*8 + l/4, c0 = (kb&3)*64 + (bsel&3)*16 + 2*(l&3), tap = kb>>2
//      bsel bit2: 0 = w_hi, 1 = w_lo (bf16 residual)
// ---------------------------------------------------------------------------
#define NRE2 (KK9*64*32*4)       // 73728
#define NWF  (NKB*8*32*32)       // 294912 uint2 records
__global__ void wprep_kernel(const float* __restrict__ off_w,
                             const float* __restrict__ mod_w,
                             const float* __restrict__ w) {
    int i = blockIdx.x * 256 + threadIdx.x;
    if (i < NRE2) {
        int r  = i & 3;
        int oc = (i >> 2) & 31;
        int c4 = (i >> 7) & 63;
        int kk = i >> 13;
        int c  = c4*4 + r;
        float v = 0.f;
        if (oc < 18)      v = off_w[(oc*CC + c)*KK9 + kk];
        else if (oc < 27) v = mod_w[((oc-18)*CC + c)*KK9 + kk];
        g_wre2[i] = v;
    } else if (i < NRE2 + NWF) {
        int j = i - NRE2;
        int lane = j & 31;
        int nt   = (j >> 5) & 31;
        int bsel = (j >> 10) & 7;
        int kb   = j >> 13;
        int kk = kb >> 2;
        int lo = bsel >> 2;
        int o  = nt*8 + (lane >> 2);
        int c0 = (kb & 3)*64 + (bsel & 3)*16 + 2*(lane & 3);
        float wv[4];
#pragma unroll
        for (int q = 0; q < 4; q++) {
            int c = c0 + (q >> 1)*8 + (q & 1);
            float f = w[(o*CC + c)*KK9 + kk];
            __nv_bfloat16 h = __float2bfloat16_rn(f);
            wv[q] = lo ? (f - __bfloat162float(h)) : f;
        }
        uint2 rec;
        rec.x = pack_bf16(wv[0], wv[1]);
        rec.y = pack_bf16(wv[2], wv[3]);
        g_wf[j] = rec;
    }
}

// ---------------------------------------------------------------------------
// Kernel 3: offset+mask conv (known correct from round 3)
// ---------------------------------------------------------------------------
#define OM_CSTR 12
__global__ void __launch_bounds__(64) offmask_kernel(const float* __restrict__ off_b,
                                                     const float* __restrict__ mod_b) {
    __shared__ __align__(16) float sX[2*32*KK9*OM_CSTR];
    __shared__ __align__(16) float4 sWr[KK9*2*32];
    __shared__ int sBase[2*32*KK9];

    int t = threadIdx.x;
    int lane = t & 31, wi = t >> 5;
    int pbase = blockIdx.x * 64;
    const float4* xp4 = (const float4*)g_xp;
    const float4* wre4 = (const float4*)g_wre2;

    for (int q = t; q < 576; q += 64) {
        int w2 = q / 288, qq = q % 288;
        int p = qq / 9, k = qq % 9;
        int pgl = pbase + w2*32 + p;
        int b = pgl / HW;
        int r = pgl % HW;
        int h = r / WW, w_ = r % WW;
        int y = h - 1 + k/3, x = w_ - 1 + k%3;
        sBase[q] = (((unsigned)y < HH) && ((unsigned)x < WW))
                   ? ((b*HH + y)*WW + x)*(CC/4) : -1;
    }
    __syncthreads();

    float* sXw = sX + wi*3456;
    const int* sBw = sBase + wi*288;
    unsigned long long acc[27];
#pragma unroll
    for (int o = 0; o < 27; o++) acc[o] = 0ull;

    for (int cb = 0; cb < 32; cb++) {
        __syncthreads();
        for (int i = t; i < 576; i += 64) {
            int oc = i & 31, kkj = i >> 5;
            sWr[kkj*32 + oc] = wre4[((kkj>>1)*64 + cb*2 + (kkj&1))*32 + oc];
        }
        for (int e = lane; e < 576; e += 32) {
            int q = e >> 1, j = e & 1;
            int bi = sBw[q];
            float4 v = make_float4(0.f, 0.f, 0.f, 0.f);
            if (bi >= 0) v = xp4[bi + cb*2 + j];
            *(float4*)&sXw[q*OM_CSTR + j*4] = v;
        }
        __syncthreads();
#pragma unroll 1
        for (int kk = 0; kk < 9; kk++) {
#pragma unroll
            for (int j = 0; j < 2; j++) {
                F4 sv;
                sv.f = *(const float4*)&sXw[(lane*9 + kk)*OM_CSTR + j*4];
                const float4* wrow = &sWr[(kk*2 + j)*32];
#pragma unroll
                for (int o = 0; o < 27; o++) {
                    F4 wv; wv.f = wrow[o];
                    acc[o] = ff2(sv.u[0], wv.u[0], acc[o]);
                    acc[o] = ff2(sv.u[1], wv.u[1], acc[o]);
                }
            }
        }
    }

    int pgl = pbase + wi*32 + lane;
#pragma unroll
    for (int o = 0; o < 27; o++) {
        float2 f = *(float2*)&acc[o];
        float r = f.x + f.y;
        float v;
        if (o < 18) v = r + off_b[o];
        else { float a = r + mod_b[o-18]; v = 2.f/(1.f + expf(-a)); }
        g_om[pgl*32 + o] = v;
    }
}

// ---------------------------------------------------------------------------
// Kernel 4: deformable conv via mma.sync bf16 (3-term hi/lo split).
// Block: 512 thr = 16 warps (4m x 4n), M=64 pos, N=256. Grid 400.
// 36 chunks of 64 channels; A tiles (s_hi, s_lo) 64x64 bf16, swizzled 128B rows,
// double-buffered. B fragments direct from g_wf (coalesced LDG.64, L2-hot).
// ---------------------------------------------------------------------------
// dynamic smem layout (bytes)
#define DSM_A    0        // union: A bufs 2x(8192 hi + 8192 lo) = 32768  /  epi 65536
#define DSM_CW   65536    // float4[9][64]  = 9216
#define DSM_CI   74752    // int4[9][64]    = 9216
#define DSM_OB   83968    // int[64]
#define DSM_BIAS 84224    // float[256]
#define DSM_TOT  85248

__device__ __forceinline__ void deform_gather(char* dsm, int pbase, int kb, int buf,
                                              int t) {
    const float4* xp4 = (const float4*)g_xp;
    const float4* sCW = (const float4*)(dsm + DSM_CW);
    const int4*   sCI = (const int4*)(dsm + DSM_CI);
    int kk = kb >> 2;
    int p = t >> 3, g = t & 7;          // 512 tasks: 64 pos x 8 groups of 8 ch
    float4 bw = sCW[kk*64 + p];
    int4 iv = sCI[kk*64 + p];
    float v[8];
    int fbase = (kb & 3)*16 + g*2;
#pragma unroll
    for (int j = 0; j < 2; j++) {
        int f = fbase + j;
        float4 a  = xp4[iv.x + f];
        float4 b2 = xp4[iv.y + f];
        float4 c2 = xp4[iv.z + f];
        float4 d2 = xp4[iv.w + f];
        v[4*j+0] = bw.x*a.x + bw.y*b2.x + bw.z*c2.x + bw.w*d2.x;
        v[4*j+1] = bw.x*a.y + bw.y*b2.y + bw.z*c2.y + bw.w*d2.y;
        v[4*j+2] = bw.x*a.z + bw.y*b2.z + bw.z*c2.z + bw.w*d2.z;
        v[4*j+3] = bw.x*a.w + bw.y*b2.w + bw.z*c2.w + bw.w*d2.w;
    }
    uint32_t hp[4], lp[4];
#pragma unroll
    for (int q = 0; q < 4; q++) {
        float a0 = v[2*q], a1 = v[2*q+1];
        __nv_bfloat16 h0 = __float2bfloat16_rn(a0);
        __nv_bfloat16 h1 = __float2bfloat16_rn(a1);
        hp[q] = ((uint32_t)__bfloat16_as_ushort(h1) << 16) | __bfloat16_as_ushort(h0);
        lp[q] = pack_bf16(a0 - __bfloat162float(h0), a1 - __bfloat162float(h1));
    }
    char* Ab = dsm + DSM_A + buf*16384;
    int off = p*128 + ((g*16) ^ ((p & 7) << 4));   // SW128 swizzle
    *(uint4*)(Ab + off)        = make_uint4(hp[0], hp[1], hp[2], hp[3]);
    *(uint4*)(Ab + 8192 + off) = make_uint4(lp[0], lp[1], lp[2], lp[3]);
}

__global__ void __launch_bounds__(512, 1) deform_kernel(const float* __restrict__ bias,
                                                        float* __restrict__ out) {
    extern __shared__ __align__(16) char dsm[];
    float4* sCW = (float4*)(dsm + DSM_CW);
    int4*   sCI = (int4*)(dsm + DSM_CI);
    int*    sOB = (int*)(dsm + DSM_OB);
    float*  sBias = (float*)(dsm + DSM_BIAS);
    uint32_t sb = smem_u32(dsm);

    int t = threadIdx.x, lane = t & 31, wid = t >> 5;
    int wm = wid >> 2, wn = wid & 3;    // 4m x 4n
    int pbase = blockIdx.x * 64;

    // corners for all 9 taps
    for (int q = t; q < 576; q += 512) {
        int tap = q >> 6, p = q & 63;
        int pgl = pbase + p;
        int b = pgl / HW, r = pgl % HW;
        int h = r / WW, w = r % WW;
        float dy = g_om[pgl*32 + 2*tap];
        float dx = g_om[pgl*32 + 2*tap + 1];
        float m  = g_om[pgl*32 + 18 + tap];
        float py = (float)(h - 1 + tap/3) + dy;
        float px = (float)(w - 1 + tap%3) + dx;
        float fy = floorf(py), fx = floorf(px);
        int y0 = (int)fy, x0 = (int)fx;
        float wy = py - fy, wx = px - fx;
        int y1 = y0 + 1, x1 = x0 + 1;
        bool vy0 = (unsigned)y0 < HH, vy1 = (unsigned)y1 < HH;
        bool vx0 = (unsigned)x0 < WW, vx1 = (unsigned)x1 < WW;
        float4 wv;
        wv.x = (1.f-wy)*(1.f-wx)*m * (float)(vy0 && vx0);
        wv.y = (1.f-wy)*wx      *m * (float)(vy0 && vx1);
        wv.z = wy*(1.f-wx)      *m * (float)(vy1 && vx0);
        wv.w = wy*wx            *m * (float)(vy1 && vx1);
        int yc0 = min(max(y0, 0), HH-1), yc1 = min(max(y1, 0), HH-1);
        int xc0 = min(max(x0, 0), WW-1), xc1 = min(max(x1, 0), WW-1);
        int rowb = b*HH;
        int4 iv;
        iv.x = ((rowb + yc0)*WW + xc0) * (CC/4);
        iv.y = ((rowb + yc0)*WW + xc1) * (CC/4);
        iv.z = ((rowb + yc1)*WW + xc0) * (CC/4);
        iv.w = ((rowb + yc1)*WW + xc1) * (CC/4);
        sCW[q] = wv;
        sCI[q] = iv;
    }
    if (t < 64) {
        int pgl = pbase + t;
        sOB[t] = (pgl / HW) * (CC*HW) + (pgl % HW);
    }
    if (t < 256) sBias[t] = bias[t];
    __syncthreads();

    deform_gather(dsm, pbase, 0, 0, t);
    __syncthreads();

    float acc[8][4];
#pragma unroll
    for (int nt = 0; nt < 8; nt++)
#pragma unroll
        for (int q = 0; q < 4; q++) acc[nt][q] = 0.f;

    int m0 = wm * 16;
    int rowterm = (m0 + (lane & 15)) * 128;
    int kterm = ((lane >> 4) & 1) * 16;
    int swzl = (lane & 7) << 4;

    for (int kb = 0; kb < NKB; kb++) {
        int buf = kb & 1;
        if (kb + 1 < NKB) deform_gather(dsm, pbase, kb + 1, buf ^ 1, t);

        uint32_t Ah = sb + DSM_A + buf*16384;
        uint32_t Al = Ah + 8192;
        const uint2* gbase = g_wf + ((size_t)kb*8*32 + wn*8) * 32 + lane;

        // hi-weight halves: A_hi and A_lo terms share B frags
#pragma unroll 1
        for (int h = 0; h < 4; h++) {
            uint2 bf[8];
#pragma unroll
            for (int nt = 0; nt < 8; nt++)
                bf[nt] = gbase[(h*32 + nt) * 32];
            int off = (h*32 + kterm) ^ swzl;
            uint32_t a0, a1, a2, a3;
            ldsm4(a0, a1, a2, a3, Ah + rowterm + off);
#pragma unroll
            for (int nt = 0; nt < 8; nt++)
                mma16816(acc[nt], a0, a1, a2, a3, bf[nt].x, bf[nt].y);
            ldsm4(a0, a1, a2, a3, Al + rowterm + off);
#pragma unroll
            for (int nt = 0; nt < 8; nt++)
                mma16816(acc[nt], a0, a1, a2, a3, bf[nt].x, bf[nt].y);
        }
        // lo-weight halves: A_hi only
#pragma unroll 1
        for (int h = 0; h < 4; h++) {
            uint2 bf[8];
#pragma unroll
            for (int nt = 0; nt < 8; nt++)
                bf[nt] = gbase[((4 + h)*32 + nt) * 32];
            int off = (h*32 + kterm) ^ swzl;
            uint32_t a0, a1, a2, a3;
            ldsm4(a0, a1, a2, a3, Ah + rowterm + off);
#pragma unroll
            for (int nt = 0; nt < 8; nt++)
                mma16816(acc[nt], a0, a1, a2, a3, bf[nt].x, bf[nt].y);
        }
        __syncthreads();
    }

    // epilogue: acc -> smem (reuse A region) -> coalesced NCHW stores
    float* sEp = (float*)(dsm + DSM_A);   // [o][m] = [256][64]
    int n0 = wn * 64;
    int rr = lane >> 2, cc = 2*(lane & 3);
#pragma unroll
    for (int nt = 0; nt < 8; nt++) {
        int n = n0 + nt*8 + cc;
        int m = m0 + rr;
        sEp[n*64 + m]         = acc[nt][0];
        sEp[(n+1)*64 + m]     = acc[nt][1];
        sEp[n*64 + m + 8]     = acc[nt][2];
        sEp[(n+1)*64 + m + 8] = acc[nt][3];
    }
    __syncthreads();
#pragma unroll
    for (int i = 0; i < 32; i++) {
        int idx = i*512 + t;
        int m = idx & 63, o = idx >> 6;
        out[sOB[m] + o*HW] = sEp[idx] + sBias[o];
    }
}

// ---------------------------------------------------------------------------
extern "C" void kernel_launch(void* const* d_in, const int* in_sizes, int n_in,
                              void* d_out, int out_size) {
    const float* x     = (const float*)d_in[0];
    const float* off_w = (const float*)d_in[1];
    const float* off_b = (const float*)d_in[2];
    const float* mod_w = (const float*)d_in[3];
    const float* mod_b = (const float*)d_in[4];
    const float* w     = (const float*)d_in[5];
    const float* b     = (const float*)d_in[6];
    float* out = (float*)d_out;

    cudaFuncSetAttribute(deform_kernel,
                         cudaFuncAttributeMaxDynamicSharedMemorySize, DSM_TOT);

    pool_h<<<(NPOS*CC)/256, 256>>>(x);
    pool_v<<<BB*HH*5*16, 256>>>();
    wprep_kernel<<<(NRE2 + NWF + 255)/256, 256>>>(off_w, mod_w, w);
    offmask_kernel<<<NPOS/64, 64>>>(off_b, mod_b);
    deform_kernel<<<NPOS/64, 512, DSM_TOT>>>(b, out);
}

// round 7
// speedup vs baseline: 4.3526x; 1.2986x over previous
#include <cuda_runtime.h>
#include <cuda_bf16.h>
#include <stdint.h>
#include <math.h>

// Problem constants
#define BB 4
#define CC 256
#define HH 80
#define WW 80
#define KK9 9
#define HW (HH*WW)
#define NPOS (BB*HW)             // 25600
#define NKB 36                   // K chunks: 9 taps x 4 chunks of 64 channels

// Scratch (device globals; no allocation allowed)
__device__ __align__(16) float g_xp[NPOS*CC];         // pooled input NHWC
__device__ __align__(16) float g_tmp[NPOS*CC];        // horizontal pool sums (NCHW)
__device__ __align__(16) float g_om[NPOS*32];         // per-pos offsets(18)+mask(9)
__device__ __align__(16) uint2 g_wf[NKB*8*32*32];     // deform W B-frags [kb][bsel][ntile][lane]
__device__ __align__(16) uint2 g_wfo[NKB*8*4*32];     // offmask W B-frags [kb][bsel][ntile(4)][lane]

// ============================ helpers ============================
__device__ __forceinline__ uint32_t smem_u32(const void* p) {
    uint32_t a;
    asm("{ .reg .u64 t; cvta.to.shared.u64 t, %1; cvt.u32.u64 %0, t; }" : "=r"(a) : "l"(p));
    return a;
}

__device__ __forceinline__ void ldsm4(uint32_t& a0, uint32_t& a1, uint32_t& a2,
                                      uint32_t& a3, uint32_t addr) {
    asm volatile("ldmatrix.sync.aligned.m8n8.x4.shared.b16 {%0,%1,%2,%3}, [%4];"
        : "=r"(a0), "=r"(a1), "=r"(a2), "=r"(a3) : "r"(addr));
}

__device__ __forceinline__ void mma16816(float* d, uint32_t a0, uint32_t a1,
                                         uint32_t a2, uint32_t a3,
                                         uint32_t b0, uint32_t b1) {
    asm volatile("mma.sync.aligned.m16n8k16.row.col.f32.bf16.bf16.f32 "
        "{%0,%1,%2,%3}, {%4,%5,%6,%7}, {%8,%9}, {%0,%1,%2,%3};"
        : "+f"(d[0]), "+f"(d[1]), "+f"(d[2]), "+f"(d[3])
        : "r"(a0), "r"(a1), "r"(a2), "r"(a3), "r"(b0), "r"(b1));
}

__device__ __forceinline__ uint32_t pack_bf16(float lo_k, float hi_k) {
    __nv_bfloat16 a = __float2bfloat16_rn(lo_k);
    __nv_bfloat16 b = __float2bfloat16_rn(hi_k);
    return ((uint32_t)__bfloat16_as_ushort(b) << 16) | __bfloat16_as_ushort(a);
}

// ---------------------------------------------------------------------------
// Kernel 1a: horizontal 3-sum (NCHW -> g_tmp NCHW)
// ---------------------------------------------------------------------------
__global__ void pool_h(const float* __restrict__ x) {
    int i = blockIdx.x * 256 + threadIdx.x;
    int w = i % WW;
    float s = x[i];
    if (w > 0)      s += x[i-1];
    if (w < WW-1)   s += x[i+1];
    g_tmp[i] = s;
}

// ---------------------------------------------------------------------------
// Kernel 1b: vertical 3-sum + /9 + transpose to NHWC (g_tmp -> g_xp)
// ---------------------------------------------------------------------------
__global__ void pool_v() {
    __shared__ float tile[16][17];
    int id = blockIdx.x;
    int c0 = (id & 15) * 16; id >>= 4;
    int w0 = (id % 5) * 16;  id /= 5;
    int h  = id % HH;
    int b  = id / HH;
    int t  = threadIdx.x;
    int ci = t >> 4, wi = t & 15;
    int c = c0 + ci, wcol = w0 + wi;
    const float* xb = g_tmp + (b*CC + c) * HW;
    float s = 0.f;
#pragma unroll
    for (int dy = -1; dy <= 1; dy++) {
        int y = h + dy;
        if (y < 0 || y >= HH) continue;
        s += xb[y*WW + wcol];
    }
    tile[ci][wi] = s * (1.f/9.f);
    __syncthreads();
    int wi2 = t >> 4, ci2 = t & 15;
    g_xp[((b*HH + h)*WW + w0 + wi2)*CC + c0 + ci2] = tile[ci2][wi2];
}

// ---------------------------------------------------------------------------
// Kernel 2: weight prep — B fragments for mma.m16n8k16.row.col (hi/lo split)
//   g_wf  (deform):  [kb][bsel(4 khalf x hi/lo)][ntile(32)][lane]
//   g_wfo (offmask): [kb][bsel][ntile(4)][lane], o<27 real else 0
// ---------------------------------------------------------------------------
#define NWF  (NKB*8*32*32)       // 294912 uint2 records
#define NWFO (NKB*8*4*32)        // 36864 uint2 records
__global__ void wprep_kernel(const float* __restrict__ off_w,
                             const float* __restrict__ mod_w,
                             const float* __restrict__ w) {
    int i = blockIdx.x * 256 + threadIdx.x;
    if (i < NWF) {
        int j = i;
        int lane = j & 31;
        int nt   = (j >> 5) & 31;
        int bsel = (j >> 10) & 7;
        int kb   = j >> 13;
        int kk = kb >> 2;
        int lo = bsel >> 2;
        int o  = nt*8 + (lane >> 2);
        int c0 = (kb & 3)*64 + (bsel & 3)*16 + 2*(lane & 3);
        float wv[4];
#pragma unroll
        for (int q = 0; q < 4; q++) {
            int c = c0 + (q >> 1)*8 + (q & 1);
            float f = w[(o*CC + c)*KK9 + kk];
            __nv_bfloat16 h = __float2bfloat16_rn(f);
            wv[q] = lo ? (f - __bfloat162float(h)) : f;
        }
        uint2 rec;
        rec.x = pack_bf16(wv[0], wv[1]);
        rec.y = pack_bf16(wv[2], wv[3]);
        g_wf[j] = rec;
    } else if (i < NWF + NWFO) {
        int j = i - NWF;
        int lane = j & 31;
        int nt   = (j >> 5) & 3;
        int bsel = (j >> 7) & 7;
        int kb   = j >> 10;
        int kk = kb >> 2;
        int lo = bsel >> 2;
        int o  = nt*8 + (lane >> 2);
        int c0 = (kb & 3)*64 + (bsel & 3)*16 + 2*(lane & 3);
        float wv[4];
#pragma unroll
        for (int q = 0; q < 4; q++) {
            int c = c0 + (q >> 1)*8 + (q & 1);
            float f = 0.f;
            if (o < 18)      f = off_w[(o*CC + c)*KK9 + kk];
            else if (o < 27) f = mod_w[((o-18)*CC + c)*KK9 + kk];
            __nv_bfloat16 h = __float2bfloat16_rn(f);
            wv[q] = lo ? (f - __bfloat162float(h)) : f;
        }
        uint2 rec;
        rec.x = pack_bf16(wv[0], wv[1]);
        rec.y = pack_bf16(wv[2], wv[3]);
        g_wfo[j] = rec;
    }
}

// ---------------------------------------------------------------------------
// Kernel 3: offset+mask conv via mma.sync bf16 (3-term hi/lo split).
// Block: 256 thr = 8 warps (4m x 2n). M=64 pos, N=32(27). Grid 400.
// A tiles identical in layout to deform's; B frags from g_wfo.
// ---------------------------------------------------------------------------
__device__ __forceinline__ void om_gather(char* sA, const int* sBase, int kb,
                                          int buf, int t) {
    const float4* xp4 = (const float4*)g_xp;
    int kk = kb >> 2;
    for (int it = t; it < 512; it += 256) {
        int p = it >> 3, g = it & 7;
        int bi = sBase[kk*64 + p];
        int fbase = (kb & 3)*16 + g*2;
        float v[8];
#pragma unroll
        for (int j = 0; j < 2; j++) {
            float4 a = make_float4(0.f, 0.f, 0.f, 0.f);
            if (bi >= 0) a = xp4[bi + fbase + j];
            v[4*j+0] = a.x; v[4*j+1] = a.y; v[4*j+2] = a.z; v[4*j+3] = a.w;
        }
        uint32_t hp[4], lp[4];
#pragma unroll
        for (int q = 0; q < 4; q++) {
            float a0 = v[2*q], a1 = v[2*q+1];
            __nv_bfloat16 h0 = __float2bfloat16_rn(a0);
            __nv_bfloat16 h1 = __float2bfloat16_rn(a1);
            hp[q] = ((uint32_t)__bfloat16_as_ushort(h1) << 16) | __bfloat16_as_ushort(h0);
            lp[q] = pack_bf16(a0 - __bfloat162float(h0), a1 - __bfloat162float(h1));
        }
        int off = p*128 + ((g*16) ^ ((p & 7) << 4));
        *(uint4*)(sA + buf*16384 + off)        = make_uint4(hp[0], hp[1], hp[2], hp[3]);
        *(uint4*)(sA + buf*16384 + 8192 + off) = make_uint4(lp[0], lp[1], lp[2], lp[3]);
    }
}

__global__ void __launch_bounds__(256) offmask_kernel(const float* __restrict__ off_b,
                                                      const float* __restrict__ mod_b) {
    __shared__ __align__(16) char sA[2*16384];
    __shared__ int sBase[576];
    uint32_t sb = smem_u32(sA);

    int t = threadIdx.x, lane = t & 31, wid = t >> 5;
    int wm = wid >> 1, wn = wid & 1;
    int pbase = blockIdx.x * 64;

    for (int q = t; q < 576; q += 256) {
        int tap = q >> 6, p = q & 63;
        int pgl = pbase + p;
        int b = pgl / HW, r = pgl % HW;
        int h = r / WW, w = r % WW;
        int y = h - 1 + tap/3, x = w - 1 + tap%3;
        sBase[q] = (((unsigned)y < HH) && ((unsigned)x < WW))
                   ? ((b*HH + y)*WW + x)*(CC/4) : -1;
    }
    __syncthreads();

    om_gather(sA, sBase, 0, 0, t);
    __syncthreads();

    float acc[2][4];
#pragma unroll
    for (int nt = 0; nt < 2; nt++)
#pragma unroll
        for (int q = 0; q < 4; q++) acc[nt][q] = 0.f;

    int rowterm = (wm*16 + (lane & 15)) * 128;
    int kterm = ((lane >> 4) & 1) * 16;
    int swzl = (lane & 7) << 4;

    for (int kb = 0; kb < NKB; kb++) {
        int buf = kb & 1;
        if (kb + 1 < NKB) om_gather(sA, sBase, kb + 1, buf ^ 1, t);

        uint32_t Ah = sb + buf*16384;
        uint32_t Al = Ah + 8192;
        const uint2* gb = g_wfo + (size_t)kb*8*4*32 + lane;

#pragma unroll 1
        for (int h = 0; h < 4; h++) {
            uint2 bf0 = gb[(h*4 + wn*2    ) * 32];
            uint2 bf1 = gb[(h*4 + wn*2 + 1) * 32];
            int off = (h*32 + kterm) ^ swzl;
            uint32_t a0, a1, a2, a3;
            ldsm4(a0, a1, a2, a3, Ah + rowterm + off);
            mma16816(acc[0], a0, a1, a2, a3, bf0.x, bf0.y);
            mma16816(acc[1], a0, a1, a2, a3, bf1.x, bf1.y);
            ldsm4(a0, a1, a2, a3, Al + rowterm + off);
            mma16816(acc[0], a0, a1, a2, a3, bf0.x, bf0.y);
            mma16816(acc[1], a0, a1, a2, a3, bf1.x, bf1.y);
        }
#pragma unroll 1
        for (int h = 0; h < 4; h++) {
            uint2 bf0 = gb[((4 + h)*4 + wn*2    ) * 32];
            uint2 bf1 = gb[((4 + h)*4 + wn*2 + 1) * 32];
            int off = (h*32 + kterm) ^ swzl;
            uint32_t a0, a1, a2, a3;
            ldsm4(a0, a1, a2, a3, Ah + rowterm + off);
            mma16816(acc[0], a0, a1, a2, a3, bf0.x, bf0.y);
            mma16816(acc[1], a0, a1, a2, a3, bf1.x, bf1.y);
        }
        __syncthreads();
    }

    // epilogue: bias / 2*sigmoid, direct stores to g_om
    int row = pbase + wm*16 + (lane >> 2);
#pragma unroll
    for (int nt = 0; nt < 2; nt++) {
        int col = (wn*2 + nt)*8 + 2*(lane & 3);
#pragma unroll
        for (int q = 0; q < 4; q++) {
            int cc = col + (q & 1);
            int rr = row + (q >> 1)*8;
            float v = acc[nt][q];
            if (cc < 18)      v = v + off_b[cc];
            else if (cc < 27) v = 2.f / (1.f + expf(-(v + mod_b[cc-18])));
            else continue;
            g_om[rr*32 + cc] = v;
        }
    }
}

// ---------------------------------------------------------------------------
// Kernel 4: deformable conv via mma.sync bf16 (3-term hi/lo split).
// Block: 512 thr = 16 warps (4m x 4n), M=64 pos, N=256. Grid 400.
// ---------------------------------------------------------------------------
// dynamic smem layout (bytes)
#define DSM_A    0        // union: A bufs 2x(8192 hi + 8192 lo) = 32768  /  epi 65536
#define DSM_CW   65536    // float4[9][64]  = 9216
#define DSM_CI   74752    // int4[9][64]    = 9216
#define DSM_OB   83968    // int[64]
#define DSM_BIAS 84224    // float[256]
#define DSM_TOT  85248

__device__ __forceinline__ void deform_gather(char* dsm, int pbase, int kb, int buf,
                                              int t) {
    const float4* xp4 = (const float4*)g_xp;
    const float4* sCW = (const float4*)(dsm + DSM_CW);
    const int4*   sCI = (const int4*)(dsm + DSM_CI);
    int kk = kb >> 2;
    int p = t >> 3, g = t & 7;          // 512 tasks: 64 pos x 8 groups of 8 ch
    float4 bw = sCW[kk*64 + p];
    int4 iv = sCI[kk*64 + p];
    float v[8];
    int fbase = (kb & 3)*16 + g*2;
#pragma unroll
    for (int j = 0; j < 2; j++) {
        int f = fbase + j;
        float4 a  = xp4[iv.x + f];
        float4 b2 = xp4[iv.y + f];
        float4 c2 = xp4[iv.z + f];
        float4 d2 = xp4[iv.w + f];
        v[4*j+0] = bw.x*a.x + bw.y*b2.x + bw.z*c2.x + bw.w*d2.x;
        v[4*j+1] = bw.x*a.y + bw.y*b2.y + bw.z*c2.y + bw.w*d2.y;
        v[4*j+2] = bw.x*a.z + bw.y*b2.z + bw.z*c2.z + bw.w*d2.z;
        v[4*j+3] = bw.x*a.w + bw.y*b2.w + bw.z*c2.w + bw.w*d2.w;
    }
    uint32_t hp[4], lp[4];
#pragma unroll
    for (int q = 0; q < 4; q++) {
        float a0 = v[2*q], a1 = v[2*q+1];
        __nv_bfloat16 h0 = __float2bfloat16_rn(a0);
        __nv_bfloat16 h1 = __float2bfloat16_rn(a1);
        hp[q] = ((uint32_t)__bfloat16_as_ushort(h1) << 16) | __bfloat16_as_ushort(h0);
        lp[q] = pack_bf16(a0 - __bfloat162float(h0), a1 - __bfloat162float(h1));
    }
    char* Ab = dsm + DSM_A + buf*16384;
    int off = p*128 + ((g*16) ^ ((p & 7) << 4));   // SW128 swizzle
    *(uint4*)(Ab + off)        = make_uint4(hp[0], hp[1], hp[2], hp[3]);
    *(uint4*)(Ab + 8192 + off) = make_uint4(lp[0], lp[1], lp[2], lp[3]);
}

__global__ void __launch_bounds__(512, 1) deform_kernel(const float* __restrict__ bias,
                                                        float* __restrict__ out) {
    extern __shared__ __align__(16) char dsm[];
    float4* sCW = (float4*)(dsm + DSM_CW);
    int4*   sCI = (int4*)(dsm + DSM_CI);
    int*    sOB = (int*)(dsm + DSM_OB);
    float*  sBias = (float*)(dsm + DSM_BIAS);
    uint32_t sb = smem_u32(dsm);

    int t = threadIdx.x, lane = t & 31, wid = t >> 5;
    int wm = wid >> 2, wn = wid & 3;    // 4m x 4n
    int pbase = blockIdx.x * 64;

    // corners for all 9 taps
    for (int q = t; q < 576; q += 512) {
        int tap = q >> 6, p = q & 63;
        int pgl = pbase + p;
        int b = pgl / HW, r = pgl % HW;
        int h = r / WW, w = r % WW;
        float dy = g_om[pgl*32 + 2*tap];
        float dx = g_om[pgl*32 + 2*tap + 1];
        float m  = g_om[pgl*32 + 18 + tap];
        float py = (float)(h - 1 + tap/3) + dy;
        float px = (float)(w - 1 + tap%3) + dx;
        float fy = floorf(py), fx = floorf(px);
        int y0 = (int)fy, x0 = (int)fx;
        float wy = py - fy, wx = px - fx;
        int y1 = y0 + 1, x1 = x0 + 1;
        bool vy0 = (unsigned)y0 < HH, vy1 = (unsigned)y1 < HH;
        bool vx0 = (unsigned)x0 < WW, vx1 = (unsigned)x1 < WW;
        float4 wv;
        wv.x = (1.f-wy)*(1.f-wx)*m * (float)(vy0 && vx0);
        wv.y = (1.f-wy)*wx      *m * (float)(vy0 && vx1);
        wv.z = wy*(1.f-wx)      *m * (float)(vy1 && vx0);
        wv.w = wy*wx            *m * (float)(vy1 && vx1);
        int yc0 = min(max(y0, 0), HH-1), yc1 = min(max(y1, 0), HH-1);
        int xc0 = min(max(x0, 0), WW-1), xc1 = min(max(x1, 0), WW-1);
        int rowb = b*HH;
        int4 iv;
        iv.x = ((rowb + yc0)*WW + xc0) * (CC/4);
        iv.y = ((rowb + yc0)*WW + xc1) * (CC/4);
        iv.z = ((rowb + yc1)*WW + xc0) * (CC/4);
        iv.w = ((rowb + yc1)*WW + xc1) * (CC/4);
        sCW[q] = wv;
        sCI[q] = iv;
    }
    if (t < 64) {
        int pgl = pbase + t;
        sOB[t] = (pgl / HW) * (CC*HW) + (pgl % HW);
    }
    if (t < 256) sBias[t] = bias[t];
    __syncthreads();

    deform_gather(dsm, pbase, 0, 0, t);
    __syncthreads();

    float acc[8][4];
#pragma unroll
    for (int nt = 0; nt < 8; nt++)
#pragma unroll
        for (int q = 0; q < 4; q++) acc[nt][q] = 0.f;

    int m0 = wm * 16;
    int rowterm = (m0 + (lane & 15)) * 128;
    int kterm = ((lane >> 4) & 1) * 16;
    int swzl = (lane & 7) << 4;

    for (int kb = 0; kb < NKB; kb++) {
        int buf = kb & 1;
        if (kb + 1 < NKB) deform_gather(dsm, pbase, kb + 1, buf ^ 1, t);

        uint32_t Ah = sb + DSM_A + buf*16384;
        uint32_t Al = Ah + 8192;
        const uint2* gbase = g_wf + ((size_t)kb*8*32 + wn*8) * 32 + lane;

        // hi-weight halves: A_hi and A_lo terms share B frags
#pragma unroll 1
        for (int h = 0; h < 4; h++) {
            uint2 bf[8];
#pragma unroll
            for (int nt = 0; nt < 8; nt++)
                bf[nt] = gbase[(h*32 + nt) * 32];
            int off = (h*32 + kterm) ^ swzl;
            uint32_t a0, a1, a2, a3;
            ldsm4(a0, a1, a2, a3, Ah + rowterm + off);
#pragma unroll
            for (int nt = 0; nt < 8; nt++)
                mma16816(acc[nt], a0, a1, a2, a3, bf[nt].x, bf[nt].y);
            ldsm4(a0, a1, a2, a3, Al + rowterm + off);
#pragma unroll
            for (int nt = 0; nt < 8; nt++)
                mma16816(acc[nt], a0, a1, a2, a3, bf[nt].x, bf[nt].y);
        }
        // lo-weight halves: A_hi only
#pragma unroll 1
        for (int h = 0; h < 4; h++) {
            uint2 bf[8];
#pragma unroll
            for (int nt = 0; nt < 8; nt++)
                bf[nt] = gbase[((4 + h)*32 + nt) * 32];
            int off = (h*32 + kterm) ^ swzl;
            uint32_t a0, a1, a2, a3;
            ldsm4(a0, a1, a2, a3, Ah + rowterm + off);
#pragma unroll
            for (int nt = 0; nt < 8; nt++)
                mma16816(acc[nt], a0, a1, a2, a3, bf[nt].x, bf[nt].y);
        }
        __syncthreads();
    }

    // epilogue: acc -> smem (reuse A region) -> coalesced NCHW stores
    float* sEp = (float*)(dsm + DSM_A);   // [o][m] = [256][64]
    int n0 = wn * 64;
    int rr = lane >> 2, cc = 2*(lane & 3);
#pragma unroll
    for (int nt = 0; nt < 8; nt++) {
        int n = n0 + nt*8 + cc;
        int m = m0 + rr;
        sEp[n*64 + m]         = acc[nt][0];
        sEp[(n+1)*64 + m]     = acc[nt][1];
        sEp[n*64 + m + 8]     = acc[nt][2];
        sEp[(n+1)*64 + m + 8] = acc[nt][3];
    }
    __syncthreads();
#pragma unroll
    for (int i = 0; i < 32; i++) {
        int idx = i*512 + t;
        int m = idx & 63, o = idx >> 6;
        out[sOB[m] + o*HW] = sEp[idx] + sBias[o];
    }
}

// ---------------------------------------------------------------------------
extern "C" void kernel_launch(void* const* d_in, const int* in_sizes, int n_in,
                              void* d_out, int out_size) {
    const float* x     = (const float*)d_in[0];
    const float* off_w = (const float*)d_in[1];
    const float* off_b = (const float*)d_in[2];
    const float* mod_w = (const float*)d_in[3];
    const float* mod_b = (const float*)d_in[4];
    const float* w     = (const float*)d_in[5];
    const float* b     = (const float*)d_in[6];
    float* out = (float*)d_out;

    cudaFuncSetAttribute(deform_kernel,
                         cudaFuncAttributeMaxDynamicSharedMemorySize, DSM_TOT);

    pool_h<<<(NPOS*CC)/256, 256>>>(x);
    pool_v<<<BB*HH*5*16, 256>>>();
    wprep_kernel<<<(NWF + NWFO + 255)/256, 256>>>(off_w, mod_w, w);
    offmask_kernel<<<NPOS/64, 256>>>(off_b, mod_b);
    deform_kernel<<<NPOS/64, 512, DSM_TOT>>>(b, out);
}